// round 5
// baseline (speedup 1.0000x reference)
#include <cuda_runtime.h>
#include <cuda_bf16.h>
#include <cstdint>
#include <math_constants.h>

// Fixed dataset shape: N=50000, E=800000, Fin=128, H=C=64
#define NMAX 50048
#define EMAX 800000
#define HC   64

// ---------------- scratch (__device__ globals; no allocation allowed) --------------
__device__ float g_h[NMAX * HC];      // h = x @ W  (per layer)
__device__ float g_x2[NMAX * HC];     // layer-2 input
__device__ float g_as[NMAX];          // alpha_src per node
__device__ float g_ad[NMAX];          // alpha_dst per node
__device__ int   g_src[EMAX];         // edge src (int32)
__device__ int   g_dst[EMAX];         // edge dst (int32)
__device__ int   g_deg[NMAX];         // in-degree histogram
__device__ int   g_row[NMAX + 1];     // CSR row starts (by dst)
__device__ int   g_cur[NMAX];         // scatter cursors
__device__ int   g_ssrc[EMAX];        // src ids grouped by dst
__device__ int   g_is32;              // 1 if edge buffer is int32

// ---------------- edge ingest -------------------------------------------------------
__global__ void k_zero_flag() { g_is32 = 0; }

// Read first E elements AS int64 (spans whole 2E*4-byte buffer if data is int32 —
// safe both ways). int64 data: all values in [0,N). int32 data: adjacent pairs
// combine to lo + hi*2^32, out of range for essentially all random edges.
__global__ void k_detect(const long long* __restrict__ ei, int E, int N) {
    int i = blockIdx.x * 256 + threadIdx.x;
    if (i >= E) return;
    long long v = ei[i];
    if (v < 0 || v >= (long long)N) g_is32 = 1;
}

__global__ void k_convert_edges(const void* __restrict__ eiv, int E, int N) {
    int i = blockIdx.x * 256 + threadIdx.x;
    if (i >= E) return;
    int s, d;
    if (g_is32) {
        const int* e = (const int*)eiv;
        s = e[i];
        d = e[E + i];
    } else {
        const long long* e = (const long long*)eiv;
        s = (int)e[i];
        d = (int)e[E + i];
    }
    // defensive clamp: wrong interpretation must yield wrong answer, not a crash
    g_src[i] = min(max(s, 0), N - 1);
    g_dst[i] = min(max(d, 0), N - 1);
}

// ---------------- CSR build (once; int atomics only) --------------------------------
__global__ void k_zero_nodes(int N) {
    int i = blockIdx.x * 256 + threadIdx.x;
    if (i < N) { g_deg[i] = 0; g_cur[i] = 0; }
}

__global__ void k_hist(int E) {
    int i = blockIdx.x * 256 + threadIdx.x;
    if (i < E) atomicAdd(&g_deg[g_dst[i]], 1);
}

// single-block exclusive scan over g_deg -> g_row, 1024 threads
__global__ void k_scan(int N) {
    __shared__ int warp_red[32];
    __shared__ int s_carry;
    int tid = threadIdx.x, lane = tid & 31, wid = tid >> 5;
    if (tid == 0) s_carry = 0;
    __syncthreads();
    for (int base = 0; base < N; base += 1024) {
        int idx = base + tid;
        int v = (idx < N) ? g_deg[idx] : 0;
        int x = v;
#pragma unroll
        for (int o = 1; o < 32; o <<= 1) {
            int t = __shfl_up_sync(0xFFFFFFFFu, x, o);
            if (lane >= o) x += t;
        }
        if (lane == 31) warp_red[wid] = x;
        __syncthreads();
        if (wid == 0) {
            int w = warp_red[lane];
#pragma unroll
            for (int o = 1; o < 32; o <<= 1) {
                int t = __shfl_up_sync(0xFFFFFFFFu, w, o);
                if (lane >= o) w += t;
            }
            warp_red[lane] = w;
        }
        __syncthreads();
        int wsum = (wid > 0) ? warp_red[wid - 1] : 0;
        int incl = x + wsum;
        int carry = s_carry;
        if (idx < N) g_row[idx] = carry + incl - v;   // exclusive
        __syncthreads();
        if (tid == 1023) s_carry = carry + incl;
        __syncthreads();
    }
    if (tid == 0) g_row[N] = s_carry;
}

__global__ void k_scatter(int E) {
    int i = blockIdx.x * 256 + threadIdx.x;
    if (i >= E) return;
    int d = g_dst[i];
    int pos = atomicAdd(&g_cur[d], 1);
    g_ssrc[g_row[d] + pos] = g_src[i];
}

// ---------------- dense math ---------------------------------------------------------
// H[N,64] = X[N,K] @ W[K,64]; 16 rows/block, 256 threads
template <int K>
__launch_bounds__(256)
__global__ void k_gemm64(const float* __restrict__ X, const float* __restrict__ W,
                         float* __restrict__ H, int N) {
    __shared__ float Ws[K * 64];
    __shared__ float Xs[K * 16];   // transposed: Xs[k*16 + r]
    int tid = threadIdx.x;
    for (int i = tid; i < K * 64; i += 256) Ws[i] = W[i];
    int row0 = blockIdx.x * 16;
    for (int i = tid; i < K * 16; i += 256) {
        int r = i / K, k = i - r * K;
        int row = row0 + r;
        Xs[k * 16 + r] = (row < N) ? X[row * K + k] : 0.f;
    }
    __syncthreads();
    int c = tid & 63, g = tid >> 6;
    float a0 = 0.f, a1 = 0.f, a2 = 0.f, a3 = 0.f;
#pragma unroll 16
    for (int k = 0; k < K; k++) {
        float w = Ws[k * 64 + c];
        float4 xv = *reinterpret_cast<const float4*>(&Xs[k * 16 + g * 4]);
        a0 += xv.x * w; a1 += xv.y * w; a2 += xv.z * w; a3 += xv.w * w;
    }
    int rb = row0 + g * 4;
    if (rb + 0 < N) H[(rb + 0) * 64 + c] = a0;
    if (rb + 1 < N) H[(rb + 1) * 64 + c] = a1;
    if (rb + 2 < N) H[(rb + 2) * 64 + c] = a2;
    if (rb + 3 < N) H[(rb + 3) * 64 + c] = a3;
}

// per-node alpha_src / alpha_dst = h . a (one warp per node); reads g_h symbol
__global__ void k_alpha(const float* __restrict__ a_s, const float* __restrict__ a_d, int N) {
    int warp = (blockIdx.x * blockDim.x + threadIdx.x) >> 5;
    int lane = threadIdx.x & 31;
    if (warp >= N) return;
    float h0 = g_h[warp * 64 + lane];
    float h1 = g_h[warp * 64 + 32 + lane];
    float vs = h0 * a_s[lane] + h1 * a_s[32 + lane];
    float vd = h0 * a_d[lane] + h1 * a_d[32 + lane];
#pragma unroll
    for (int o = 16; o > 0; o >>= 1) {
        vs += __shfl_down_sync(0xFFFFFFFFu, vs, o);
        vd += __shfl_down_sync(0xFFFFFFFFu, vd, o);
    }
    if (lane == 0) { g_as[warp] = vs; g_ad[warp] = vd; }
}

// ---------------- fused GAT aggregation: one warp per dst node ----------------------
__global__ void k_gat(const float* __restrict__ bias, float* __restrict__ outbuf,
                      int do_relu, int N) {
    int warp = (blockIdx.x * blockDim.x + threadIdx.x) >> 5;
    int lane = threadIdx.x & 31;
    if (warp >= N) return;
    int beg = g_row[warp], end = g_row[warp + 1];
    float ad = g_ad[warp];

    // pass 1: segment max of leakyrelu(as[src]+ad)
    float m = -CUDART_INF_F;
    for (int i = beg + lane; i < end; i += 32) {
        float e = g_as[g_ssrc[i]] + ad;
        e = (e > 0.f) ? e : 0.2f * e;
        m = fmaxf(m, e);
    }
#pragma unroll
    for (int o = 16; o > 0; o >>= 1)
        m = fmaxf(m, __shfl_xor_sync(0xFFFFFFFFu, m, o));

    // pass 2: p = exp(e-m) lane-parallel; acc += p * h[src,:] via shfl broadcast
    float acc0 = 0.f, acc1 = 0.f, ssum = 0.f;
    for (int base = beg; base < end; base += 32) {
        int i = base + lane;
        int srcl = 0;
        float p = 0.f;
        if (i < end) {
            srcl = g_ssrc[i];
            float e = g_as[srcl] + ad;
            e = (e > 0.f) ? e : 0.2f * e;
            p = expf(e - m);
            ssum += p;
        }
        int cnt = min(32, end - base);
        for (int j = 0; j < cnt; j++) {
            float pj = __shfl_sync(0xFFFFFFFFu, p, j);
            int   sj = __shfl_sync(0xFFFFFFFFu, srcl, j);
            acc0 += pj * g_h[sj * 64 + lane];
            acc1 += pj * g_h[sj * 64 + 32 + lane];
        }
    }
#pragma unroll
    for (int o = 16; o > 0; o >>= 1)
        ssum += __shfl_xor_sync(0xFFFFFFFFu, ssum, o);

    float inv = 1.f / (ssum + 1e-16f);   // deg==0: acc=0, matches ref (0/eps + b)
    float r0 = acc0 * inv + bias[lane];
    float r1 = acc1 * inv + bias[32 + lane];
    if (do_relu) { r0 = fmaxf(r0, 0.f); r1 = fmaxf(r1, 0.f); }
    outbuf[warp * 64 + lane]      = r0;
    outbuf[warp * 64 + 32 + lane] = r1;
}

// ---------------- launch -------------------------------------------------------------
extern "C" void kernel_launch(void* const* d_in, const int* in_sizes, int n_in,
                              void* d_out, int out_size) {
    // ---- size-driven role assignment (robust to metadata ordering) ----
    int ix = 0, ie = 0, iw1 = 0, iw2 = 0;
    for (int i = 1; i < n_in; i++) if (in_sizes[i] > in_sizes[ix]) ix = i;
    ie = (ix == 0) ? 1 : 0;
    for (int i = 0; i < n_in; i++) if (i != ix && in_sizes[i] > in_sizes[ie]) ie = i;
    iw1 = -1;
    for (int i = 0; i < n_in; i++) {
        if (i == ix || i == ie) continue;
        if (iw1 < 0 || in_sizes[i] > in_sizes[iw1]) iw1 = i;
    }
    iw2 = -1;
    for (int i = 0; i < n_in; i++) {
        if (i == ix || i == ie || i == iw1) continue;
        if (iw2 < 0 || in_sizes[i] > in_sizes[iw2]) iw2 = i;
    }
    int rv[6]; int nrv = 0;
    for (int i = 0; i < n_in && nrv < 6; i++)
        if (i != ix && i != ie && i != iw1 && i != iw2) rv[nrv++] = i;

    int ias1, iad1, ib1, ias2, iad2, ib2;
    if (ix == 0) {  // signature/dict order: x, ei, W1, a_src1, a_dst1, b1, W2, a_src2, a_dst2, b2
        ias1 = rv[0]; iad1 = rv[1]; ib1 = rv[2];
        ias2 = rv[3]; iad2 = rv[4]; ib2 = rv[5];
    } else {        // alphabetical: W1, W2, a_dst1, a_dst2, a_src1, a_src2, b1, b2, ei, x
        iad1 = rv[0]; iad2 = rv[1]; ias1 = rv[2];
        ias2 = rv[3]; ib1  = rv[4]; ib2  = rv[5];
    }

    const float* x   = (const float*)d_in[ix];
    const void*  ei  = d_in[ie];
    const float* W1  = (const float*)d_in[iw1];
    const float* as1 = (const float*)d_in[ias1];
    const float* ad1 = (const float*)d_in[iad1];
    const float* b1  = (const float*)d_in[ib1];
    const float* W2  = (const float*)d_in[iw2];
    const float* as2 = (const float*)d_in[ias2];
    const float* ad2 = (const float*)d_in[iad2];
    const float* b2  = (const float*)d_in[ib2];
    float*       out = (float*)d_out;

    const int Hd  = in_sizes[ias1];         // 64
    const int Fin = in_sizes[iw1] / Hd;     // 128
    const int N   = in_sizes[ix] / Fin;     // 50000
    const int E   = in_sizes[ie] / 2;       // 800000

    // *** THE FIX: real device addresses for __device__ globals passed as args ***
    float *p_h = nullptr, *p_x2 = nullptr;
    cudaGetSymbolAddress((void**)&p_h,  g_h);
    cudaGetSymbolAddress((void**)&p_x2, g_x2);

    const int B_E    = (E + 255) / 256;
    const int B_N    = (N + 255) / 256;
    const int B_WARP = (N * 32 + 255) / 256;
    const int B_ROWS = (N + 15) / 16;

    // edge ingest + CSR build (shared by both layers)
    k_zero_flag<<<1, 1>>>();
    k_detect<<<B_E, 256>>>((const long long*)ei, E, N);
    k_convert_edges<<<B_E, 256>>>(ei, E, N);
    k_zero_nodes<<<B_N, 256>>>(N);
    k_hist<<<B_E, 256>>>(E);
    k_scan<<<1, 1024>>>(N);
    k_scatter<<<B_E, 256>>>(E);

    // ---- layer 1 ----
    k_gemm64<128><<<B_ROWS, 256>>>(x, W1, p_h, N);
    k_alpha<<<B_WARP, 256>>>(as1, ad1, N);
    k_gat<<<B_WARP, 256>>>(b1, p_x2, 1, N);

    // ---- layer 2 ----
    k_gemm64<64><<<B_ROWS, 256>>>(p_x2, W2, p_h, N);
    k_alpha<<<B_WARP, 256>>>(as2, ad2, N);
    k_gat<<<B_WARP, 256>>>(b2, out, 0, N);
}

// round 6
// speedup vs baseline: 1.1981x; 1.1981x over previous
#include <cuda_runtime.h>
#include <cuda_bf16.h>
#include <cstdint>
#include <math_constants.h>

// Fixed dataset shape: N=50000, E=800000, Fin=128, H=C=64
#define NMAX 50048
#define EMAX 800000
#define HC   64

// ---------------- scratch (__device__ globals; no allocation allowed) --------------
__device__ float g_h[NMAX * HC];      // h = x @ W  (per layer)
__device__ float g_x2[NMAX * HC];     // layer-2 input
__device__ float g_as[NMAX];          // alpha_src per node
__device__ float g_ad[NMAX];          // alpha_dst per node
__device__ int   g_src[EMAX];         // edge src (int32)
__device__ int   g_dst[EMAX];         // edge dst (int32)
__device__ int   g_deg[NMAX];         // in-degree histogram
__device__ int   g_row[NMAX + 4];     // CSR row starts (by dst), int4-padded
__device__ int   g_cur[NMAX];         // scatter cursors
__device__ int   g_ssrc[EMAX];        // src ids grouped by dst

// ---------------- fused ingest: dtype-detect + convert + histogram ------------------
// Zero deg/cur (whole padded range so the int4 scan sees zeros beyond N)
__global__ void k_zero() {
    int i = blockIdx.x * 256 + threadIdx.x;
    if (i < NMAX) { g_deg[i] = 0; g_cur[i] = 0; }
}

// Block-local dtype vote: read element i AS int64 (spans exactly the buffer if the
// data is int32 — safe both ways). int64 data: every value lands in [0,N) -> every
// block votes "int64". int32 data: adjacent index pairs combine to lo + hi*2^32,
// out of [0,N) unless hi==0 AND lo<N; all-256-in-range probability ~ (2e-5)^256 ~ 0.
__global__ void k_ingest(const void* __restrict__ eiv, int E, int N) {
    int i = blockIdx.x * 256 + threadIdx.x;
    long long v = 0; int ok = 1;
    if (i < E) {
        v = ((const long long*)eiv)[i];
        ok = (v >= 0 && v < (long long)N) ? 1 : 0;
    }
    int all64 = __syncthreads_and(ok);
    if (i >= E) return;
    int s, d;
    if (all64) {
        s = (int)v;
        d = (int)((const long long*)eiv)[E + i];
    } else {
        const int* e = (const int*)eiv;
        s = e[i];
        d = e[E + i];
    }
    s = min(max(s, 0), N - 1);           // defensive: never crash on bad data
    d = min(max(d, 0), N - 1);
    g_src[i] = s;
    g_dst[i] = d;
    atomicAdd(&g_deg[d], 1);
}

// single-block exclusive scan over g_deg -> g_row; int4, 4096 elems/iteration
__global__ void k_scan() {
    __shared__ int warp_red[32];
    __shared__ int s_carry;
    int tid = threadIdx.x, lane = tid & 31, wid = tid >> 5;
    if (tid == 0) s_carry = 0;
    __syncthreads();
    const int4* deg4 = (const int4*)g_deg;
    int4*       row4 = (int4*)g_row;
    const int total4 = NMAX / 4;
    for (int base = 0; base < total4; base += 1024) {
        int idx = base + tid;
        int4 v = (idx < total4) ? deg4[idx] : make_int4(0, 0, 0, 0);
        int s = v.x + v.y + v.z + v.w;
        int x = s;
#pragma unroll
        for (int o = 1; o < 32; o <<= 1) {
            int t = __shfl_up_sync(0xFFFFFFFFu, x, o);
            if (lane >= o) x += t;
        }
        if (lane == 31) warp_red[wid] = x;
        __syncthreads();
        if (wid == 0) {
            int w = warp_red[lane];
#pragma unroll
            for (int o = 1; o < 32; o <<= 1) {
                int t = __shfl_up_sync(0xFFFFFFFFu, w, o);
                if (lane >= o) w += t;
            }
            warp_red[lane] = w;
        }
        __syncthreads();
        int wsum = (wid > 0) ? warp_red[wid - 1] : 0;
        int incl = x + wsum;
        int carry = s_carry;
        if (idx < total4) {
            int e0 = carry + incl - s;   // exclusive prefix of this int4 group
            int4 r;
            r.x = e0;
            r.y = e0 + v.x;
            r.z = e0 + v.x + v.y;
            r.w = e0 + v.x + v.y + v.z;
            row4[idx] = r;
        }
        __syncthreads();
        if (tid == 1023) s_carry = carry + incl;
        __syncthreads();
    }
}

__global__ void k_scatter(int E) {
    int i = blockIdx.x * 256 + threadIdx.x;
    if (i >= E) return;
    int d = g_dst[i];
    int pos = atomicAdd(&g_cur[d], 1);
    g_ssrc[g_row[d] + pos] = g_src[i];
}

// ---------------- dense math ---------------------------------------------------------
// H[N,64] = X[N,K] @ W[K,64]; 16 rows/block, 256 threads
template <int K>
__launch_bounds__(256)
__global__ void k_gemm64(const float* __restrict__ X, const float* __restrict__ W,
                         float* __restrict__ H, int N) {
    __shared__ float Ws[K * 64];
    __shared__ float Xs[K * 16];   // transposed: Xs[k*16 + r]
    int tid = threadIdx.x;
    for (int i = tid; i < K * 64; i += 256) Ws[i] = W[i];
    int row0 = blockIdx.x * 16;
    for (int i = tid; i < K * 16; i += 256) {
        int r = i / K, k = i - r * K;
        int row = row0 + r;
        Xs[k * 16 + r] = (row < N) ? X[row * K + k] : 0.f;
    }
    __syncthreads();
    int c = tid & 63, g = tid >> 6;
    float a0 = 0.f, a1 = 0.f, a2 = 0.f, a3 = 0.f;
#pragma unroll 16
    for (int k = 0; k < K; k++) {
        float w = Ws[k * 64 + c];
        float4 xv = *reinterpret_cast<const float4*>(&Xs[k * 16 + g * 4]);
        a0 += xv.x * w; a1 += xv.y * w; a2 += xv.z * w; a3 += xv.w * w;
    }
    int rb = row0 + g * 4;
    if (rb + 0 < N) H[(rb + 0) * 64 + c] = a0;
    if (rb + 1 < N) H[(rb + 1) * 64 + c] = a1;
    if (rb + 2 < N) H[(rb + 2) * 64 + c] = a2;
    if (rb + 3 < N) H[(rb + 3) * 64 + c] = a3;
}

// per-node alpha_src / alpha_dst = h . a (one warp per node, float2 lanes)
__global__ void k_alpha(const float* __restrict__ a_s, const float* __restrict__ a_d, int N) {
    int warp = (blockIdx.x * blockDim.x + threadIdx.x) >> 5;
    int lane = threadIdx.x & 31;
    if (warp >= N) return;
    const float2* h2 = (const float2*)g_h;
    float2 hv  = h2[warp * 32 + lane];
    float2 asv = ((const float2*)a_s)[lane];
    float2 adv = ((const float2*)a_d)[lane];
    float vs = hv.x * asv.x + hv.y * asv.y;
    float vd = hv.x * adv.x + hv.y * adv.y;
#pragma unroll
    for (int o = 16; o > 0; o >>= 1) {
        vs += __shfl_down_sync(0xFFFFFFFFu, vs, o);
        vd += __shfl_down_sync(0xFFFFFFFFu, vd, o);
    }
    if (lane == 0) { g_as[warp] = vs; g_ad[warp] = vd; }
}

// ---------------- fused GAT aggregation: one warp per dst node, SINGLE pass ---------
// Softmax is shift-invariant: sum(p*h)/sum(p) with p=exp(e) equals the max-shifted
// reference exactly (scores are O(1); fp32 exp overflow needs |e|>88 — impossible here).
__global__ void k_gat(const float* __restrict__ bias, float* __restrict__ outbuf,
                      int do_relu, int N) {
    int warp = (blockIdx.x * blockDim.x + threadIdx.x) >> 5;
    int lane = threadIdx.x & 31;
    if (warp >= N) return;
    int beg = g_row[warp], end = g_row[warp + 1];
    float ad = g_ad[warp];
    const float2* h2 = (const float2*)g_h;

    float accx = 0.f, accy = 0.f, ssum = 0.f;
    for (int base = beg; base < end; base += 32) {
        int i = base + lane;
        int srcl = 0;
        float p = 0.f;
        if (i < end) {
            srcl = g_ssrc[i];
            float e = g_as[srcl] + ad;
            e = (e > 0.f) ? e : 0.2f * e;      // LeakyReLU(0.2)
            p = __expf(e);
            ssum += p;
        }
        int cnt = min(32, end - base);
        for (int j = 0; j < cnt; j++) {
            float pj = __shfl_sync(0xFFFFFFFFu, p, j);
            int   sj = __shfl_sync(0xFFFFFFFFu, srcl, j);
            float2 hv = h2[sj * 32 + lane];
            accx += pj * hv.x;
            accy += pj * hv.y;
        }
    }
#pragma unroll
    for (int o = 16; o > 0; o >>= 1)
        ssum += __shfl_xor_sync(0xFFFFFFFFu, ssum, o);

    float inv = 1.f / (ssum + 1e-16f);   // deg==0: acc=0 -> out=bias, matches ref
    float2 bv = ((const float2*)bias)[lane];
    float2 r;
    r.x = accx * inv + bv.x;
    r.y = accy * inv + bv.y;
    if (do_relu) { r.x = fmaxf(r.x, 0.f); r.y = fmaxf(r.y, 0.f); }
    ((float2*)outbuf)[warp * 32 + lane] = r;
}

// ---------------- launch -------------------------------------------------------------
extern "C" void kernel_launch(void* const* d_in, const int* in_sizes, int n_in,
                              void* d_out, int out_size) {
    // ---- size-driven role assignment (robust to metadata ordering) ----
    int ix = 0, ie = 0, iw1 = 0, iw2 = 0;
    for (int i = 1; i < n_in; i++) if (in_sizes[i] > in_sizes[ix]) ix = i;
    ie = (ix == 0) ? 1 : 0;
    for (int i = 0; i < n_in; i++) if (i != ix && in_sizes[i] > in_sizes[ie]) ie = i;
    iw1 = -1;
    for (int i = 0; i < n_in; i++) {
        if (i == ix || i == ie) continue;
        if (iw1 < 0 || in_sizes[i] > in_sizes[iw1]) iw1 = i;
    }
    iw2 = -1;
    for (int i = 0; i < n_in; i++) {
        if (i == ix || i == ie || i == iw1) continue;
        if (iw2 < 0 || in_sizes[i] > in_sizes[iw2]) iw2 = i;
    }
    int rv[6]; int nrv = 0;
    for (int i = 0; i < n_in && nrv < 6; i++)
        if (i != ix && i != ie && i != iw1 && i != iw2) rv[nrv++] = i;

    int ias1, iad1, ib1, ias2, iad2, ib2;
    if (ix == 0) {  // signature/dict order: x, ei, W1, a_src1, a_dst1, b1, W2, a_src2, a_dst2, b2
        ias1 = rv[0]; iad1 = rv[1]; ib1 = rv[2];
        ias2 = rv[3]; iad2 = rv[4]; ib2 = rv[5];
    } else {        // alphabetical: W1, W2, a_dst1, a_dst2, a_src1, a_src2, b1, b2, ei, x
        iad1 = rv[0]; iad2 = rv[1]; ias1 = rv[2];
        ias2 = rv[3]; ib1  = rv[4]; ib2  = rv[5];
    }

    const float* x   = (const float*)d_in[ix];
    const void*  ei  = d_in[ie];
    const float* W1  = (const float*)d_in[iw1];
    const float* as1 = (const float*)d_in[ias1];
    const float* ad1 = (const float*)d_in[iad1];
    const float* b1  = (const float*)d_in[ib1];
    const float* W2  = (const float*)d_in[iw2];
    const float* as2 = (const float*)d_in[ias2];
    const float* ad2 = (const float*)d_in[iad2];
    const float* b2  = (const float*)d_in[ib2];
    float*       out = (float*)d_out;

    const int Hd  = in_sizes[ias1];         // 64
    const int Fin = in_sizes[iw1] / Hd;     // 128
    const int N   = in_sizes[ix] / Fin;     // 50000
    const int E   = in_sizes[ie] / 2;       // 800000

    // real device addresses for __device__ globals passed as kernel args
    float *p_h = nullptr, *p_x2 = nullptr;
    cudaGetSymbolAddress((void**)&p_h,  g_h);
    cudaGetSymbolAddress((void**)&p_x2, g_x2);

    const int B_E    = (E + 255) / 256;
    const int B_NM   = (NMAX + 255) / 256;
    const int B_WARP = (N * 32 + 255) / 256;
    const int B_ROWS = (N + 15) / 16;

    // edge ingest + CSR build (shared by both layers) — 4 launches
    k_zero<<<B_NM, 256>>>();
    k_ingest<<<B_E, 256>>>(ei, E, N);
    k_scan<<<1, 1024>>>();
    k_scatter<<<B_E, 256>>>(E);

    // ---- layer 1 ----
    k_gemm64<128><<<B_ROWS, 256>>>(x, W1, p_h, N);
    k_alpha<<<B_WARP, 256>>>(as1, ad1, N);
    k_gat<<<B_WARP, 256>>>(b1, p_x2, 1, N);

    // ---- layer 2 ----
    k_gemm64<64><<<B_ROWS, 256>>>(p_x2, W2, p_h, N);
    k_alpha<<<B_WARP, 256>>>(as2, ad2, N);
    k_gat<<<B_WARP, 256>>>(b2, out, 0, N);
}

// round 7
// speedup vs baseline: 1.2714x; 1.0612x over previous
#include <cuda_runtime.h>
#include <cuda_fp16.h>
#include <cstdint>
#include <math_constants.h>

// Fixed dataset shape: N=50000, E=800000, Fin=128, H=C=64
#define NMAX 50048
#define EMAX 800000
#define HC   64

// ---------------- scratch (__device__ globals; no allocation allowed) --------------
__device__ __half2 g_h2[NMAX * 32];   // h = x @ W, fp16x2 (channel pairs)
__device__ float   g_x2[NMAX * HC];   // layer-2 input (fp32)
__device__ float   g_as[NMAX];        // alpha_src per node
__device__ float   g_ad[NMAX];        // alpha_dst per node
__device__ int     g_src[EMAX];       // edge src
__device__ int     g_dst[EMAX];       // edge dst
__device__ int     g_rank[EMAX];      // rank of edge within its dst row
__device__ int     g_deg[NMAX];       // in-degree histogram
__device__ int     g_row[NMAX + 4];   // CSR row starts (int4-padded)
__device__ int     g_ssrc[EMAX];      // src ids grouped by dst

// ---------------- ingest: dtype-detect + convert + histogram + rank -----------------
__global__ void k_zero() {
    int i = blockIdx.x * 256 + threadIdx.x;
    if (i < NMAX) g_deg[i] = 0;
}

// Block-local dtype vote: read element i AS int64 (spans exactly the buffer if the
// data is int32 — safe both ways). int64 data: every value in [0,N) -> block votes
// int64. int32 data: adjacent pairs combine to lo + hi*2^32, essentially never all
// in range for a whole 256-thread block.
__global__ void k_ingest(const void* __restrict__ eiv, int E, int N) {
    int i = blockIdx.x * 256 + threadIdx.x;
    long long v = 0; int ok = 1;
    if (i < E) {
        v = ((const long long*)eiv)[i];
        ok = (v >= 0 && v < (long long)N) ? 1 : 0;
    }
    int all64 = __syncthreads_and(ok);
    if (i >= E) return;
    int s, d;
    if (all64) {
        s = (int)v;
        d = (int)((const long long*)eiv)[E + i];
    } else {
        const int* e = (const int*)eiv;
        s = e[i];
        d = e[E + i];
    }
    s = min(max(s, 0), N - 1);
    d = min(max(d, 0), N - 1);
    g_src[i] = s;
    g_dst[i] = d;
    g_rank[i] = atomicAdd(&g_deg[d], 1);   // rank doubles as histogram
}

// single-block exclusive scan over g_deg -> g_row; int4, 4096 elems/iteration
__global__ void k_scan() {
    __shared__ int warp_red[32];
    __shared__ int s_carry;
    int tid = threadIdx.x, lane = tid & 31, wid = tid >> 5;
    if (tid == 0) s_carry = 0;
    __syncthreads();
    const int4* deg4 = (const int4*)g_deg;
    int4*       row4 = (int4*)g_row;
    const int total4 = NMAX / 4;
    for (int base = 0; base < total4; base += 1024) {
        int idx = base + tid;
        int4 v = (idx < total4) ? deg4[idx] : make_int4(0, 0, 0, 0);
        int s = v.x + v.y + v.z + v.w;
        int x = s;
#pragma unroll
        for (int o = 1; o < 32; o <<= 1) {
            int t = __shfl_up_sync(0xFFFFFFFFu, x, o);
            if (lane >= o) x += t;
        }
        if (lane == 31) warp_red[wid] = x;
        __syncthreads();
        if (wid == 0) {
            int w = warp_red[lane];
#pragma unroll
            for (int o = 1; o < 32; o <<= 1) {
                int t = __shfl_up_sync(0xFFFFFFFFu, w, o);
                if (lane >= o) w += t;
            }
            warp_red[lane] = w;
        }
        __syncthreads();
        int wsum = (wid > 0) ? warp_red[wid - 1] : 0;
        int incl = x + wsum;
        int carry = s_carry;
        if (idx < total4) {
            int e0 = carry + incl - s;
            int4 r;
            r.x = e0;
            r.y = e0 + v.x;
            r.z = e0 + v.x + v.y;
            r.w = e0 + v.x + v.y + v.z;
            row4[idx] = r;
        }
        __syncthreads();
        if (tid == 1023) s_carry = carry + incl;
        __syncthreads();
    }
}

// atomic-free scatter using precomputed ranks
__global__ void k_scatter(int E) {
    int i = blockIdx.x * 256 + threadIdx.x;
    if (i >= E) return;
    g_ssrc[g_row[g_dst[i]] + g_rank[i]] = g_src[i];
}

// ---------------- GEMM + fused alpha + fp16 h store ---------------------------------
// H[N,64] = X[N,K] @ W[K,64]; 16 rows/block, 256 threads (64 cols x 4 row-groups).
// Epilogue: g_h2 (fp16 channel pairs), g_as/g_ad = H . a_src / a_dst (block reduce).
template <int K>
__launch_bounds__(256)
__global__ void k_gemm64(const float* __restrict__ X, const float* __restrict__ W,
                         const float* __restrict__ avs, const float* __restrict__ avd,
                         int N) {
    __shared__ float Ws[K * 64];
    __shared__ float Xs[K * 16];         // transposed: Xs[k*16 + r]
    __shared__ float red[8][4][2];       // [warp][row-in-group][src/dst]
    int tid = threadIdx.x;
    for (int i = tid; i < K * 64; i += 256) Ws[i] = W[i];
    int row0 = blockIdx.x * 16;
    for (int i = tid; i < K * 16; i += 256) {
        int r = i / K, k = i - r * K;
        int row = row0 + r;
        Xs[k * 16 + r] = (row < N) ? X[row * K + k] : 0.f;
    }
    __syncthreads();
    int c = tid & 63, g = tid >> 6, wid = tid >> 5, lane = tid & 31;
    float a0 = 0.f, a1 = 0.f, a2 = 0.f, a3 = 0.f;
#pragma unroll 16
    for (int k = 0; k < K; k++) {
        float w = Ws[k * 64 + c];
        float4 xv = *reinterpret_cast<const float4*>(&Xs[k * 16 + g * 4]);
        a0 += xv.x * w; a1 += xv.y * w; a2 += xv.z * w; a3 += xv.w * w;
    }
    int rb = row0 + g * 4;

    // ---- fp16 h store: pair (even c, odd c+1) — both lanes in the same warp ----
    float b0 = __shfl_down_sync(0xFFFFFFFFu, a0, 1);
    float b1 = __shfl_down_sync(0xFFFFFFFFu, a1, 1);
    float b2 = __shfl_down_sync(0xFFFFFFFFu, a2, 1);
    float b3 = __shfl_down_sync(0xFFFFFFFFu, a3, 1);
    if ((c & 1) == 0) {
        int cc = c >> 1;
        if (rb + 0 < N) g_h2[(rb + 0) * 32 + cc] = __floats2half2_rn(a0, b0);
        if (rb + 1 < N) g_h2[(rb + 1) * 32 + cc] = __floats2half2_rn(a1, b1);
        if (rb + 2 < N) g_h2[(rb + 2) * 32 + cc] = __floats2half2_rn(a2, b2);
        if (rb + 3 < N) g_h2[(rb + 3) * 32 + cc] = __floats2half2_rn(a3, b3);
    }

    // ---- fused alpha: as[row] = sum_c h[row][c]*a_src[c] (and a_dst) ----
    float asc = __ldg(&avs[c]), adc = __ldg(&avd[c]);
    float s0 = a0 * asc, s1 = a1 * asc, s2 = a2 * asc, s3 = a3 * asc;
    float d0 = a0 * adc, d1 = a1 * adc, d2 = a2 * adc, d3 = a3 * adc;
#pragma unroll
    for (int o = 16; o > 0; o >>= 1) {
        s0 += __shfl_down_sync(0xFFFFFFFFu, s0, o);
        s1 += __shfl_down_sync(0xFFFFFFFFu, s1, o);
        s2 += __shfl_down_sync(0xFFFFFFFFu, s2, o);
        s3 += __shfl_down_sync(0xFFFFFFFFu, s3, o);
        d0 += __shfl_down_sync(0xFFFFFFFFu, d0, o);
        d1 += __shfl_down_sync(0xFFFFFFFFu, d1, o);
        d2 += __shfl_down_sync(0xFFFFFFFFu, d2, o);
        d3 += __shfl_down_sync(0xFFFFFFFFu, d3, o);
    }
    if (lane == 0) {
        red[wid][0][0] = s0; red[wid][1][0] = s1; red[wid][2][0] = s2; red[wid][3][0] = s3;
        red[wid][0][1] = d0; red[wid][1][1] = d1; red[wid][2][1] = d2; red[wid][3][1] = d3;
    }
    __syncthreads();
    if (tid < 16) {
        int gg = tid >> 2, rr = tid & 3;
        int row = row0 + tid;             // row0 + gg*4 + rr == row0 + tid
        if (row < N) {
            g_as[row] = red[2 * gg][rr][0] + red[2 * gg + 1][rr][0];
            g_ad[row] = red[2 * gg][rr][1] + red[2 * gg + 1][rr][1];
        }
    }
}

// ---------------- fused GAT aggregation: one warp per dst node ----------------------
// Shift-free softmax (scores are O(1); fp32 exp cannot overflow here):
// out = sum(exp(e)*h[src]) / sum(exp(e)). MLP-8 gather batching hides L2 latency.
__global__ void k_gat(const float* __restrict__ bias, float* __restrict__ outbuf,
                      int do_relu, int N) {
    int warp = (blockIdx.x * blockDim.x + threadIdx.x) >> 5;
    int lane = threadIdx.x & 31;
    if (warp >= N) return;
    int beg = g_row[warp], end = g_row[warp + 1];
    float ad = g_ad[warp];
    const uint32_t* h2u = (const uint32_t*)g_h2;

    float accx = 0.f, accy = 0.f, ssum = 0.f;
    for (int base = beg; base < end; base += 32) {
        int i = base + lane;
        int srcl = 0;
        float p = 0.f;
        if (i < end) {
            srcl = g_ssrc[i];
            float e = g_as[srcl] + ad;
            e = (e > 0.f) ? e : 0.2f * e;      // LeakyReLU(0.2)
            p = __expf(e);
            ssum += p;
        }
        int cnt = min(32, end - base);
        for (int c0 = 0; c0 < cnt; c0 += 8) {
            uint32_t hw[8]; float pw[8];
#pragma unroll
            for (int j = 0; j < 8; j++) {
                int jj = c0 + j;
                float pv = __shfl_sync(0xFFFFFFFFu, p, jj & 31);
                int   sv = __shfl_sync(0xFFFFFFFFu, srcl, jj & 31);
                pw[j] = (jj < cnt) ? pv : 0.f;
                hw[j] = h2u[sv * 32 + lane];   // sv always valid; pw gates contribution
            }
#pragma unroll
            for (int j = 0; j < 8; j++) {
                float2 hv = __half22float2(*reinterpret_cast<__half2*>(&hw[j]));
                accx += pw[j] * hv.x;
                accy += pw[j] * hv.y;
            }
        }
    }
#pragma unroll
    for (int o = 16; o > 0; o >>= 1)
        ssum += __shfl_xor_sync(0xFFFFFFFFu, ssum, o);

    float inv = 1.f / (ssum + 1e-16f);   // deg==0: acc=0 -> out=bias, matches ref
    float2 bv = ((const float2*)bias)[lane];
    float2 r;
    r.x = accx * inv + bv.x;
    r.y = accy * inv + bv.y;
    if (do_relu) { r.x = fmaxf(r.x, 0.f); r.y = fmaxf(r.y, 0.f); }
    ((float2*)outbuf)[warp * 32 + lane] = r;
}

// ---------------- launch -------------------------------------------------------------
extern "C" void kernel_launch(void* const* d_in, const int* in_sizes, int n_in,
                              void* d_out, int out_size) {
    // ---- size-driven role assignment (robust to metadata ordering) ----
    int ix = 0, ie = 0, iw1 = 0, iw2 = 0;
    for (int i = 1; i < n_in; i++) if (in_sizes[i] > in_sizes[ix]) ix = i;
    ie = (ix == 0) ? 1 : 0;
    for (int i = 0; i < n_in; i++) if (i != ix && in_sizes[i] > in_sizes[ie]) ie = i;
    iw1 = -1;
    for (int i = 0; i < n_in; i++) {
        if (i == ix || i == ie) continue;
        if (iw1 < 0 || in_sizes[i] > in_sizes[iw1]) iw1 = i;
    }
    iw2 = -1;
    for (int i = 0; i < n_in; i++) {
        if (i == ix || i == ie || i == iw1) continue;
        if (iw2 < 0 || in_sizes[i] > in_sizes[iw2]) iw2 = i;
    }
    int rv[6]; int nrv = 0;
    for (int i = 0; i < n_in && nrv < 6; i++)
        if (i != ix && i != ie && i != iw1 && i != iw2) rv[nrv++] = i;

    int ias1, iad1, ib1, ias2, iad2, ib2;
    if (ix == 0) {  // signature/dict order
        ias1 = rv[0]; iad1 = rv[1]; ib1 = rv[2];
        ias2 = rv[3]; iad2 = rv[4]; ib2 = rv[5];
    } else {        // alphabetical order
        iad1 = rv[0]; iad2 = rv[1]; ias1 = rv[2];
        ias2 = rv[3]; ib1  = rv[4]; ib2  = rv[5];
    }

    const float* x   = (const float*)d_in[ix];
    const void*  ei  = d_in[ie];
    const float* W1  = (const float*)d_in[iw1];
    const float* as1 = (const float*)d_in[ias1];
    const float* ad1 = (const float*)d_in[iad1];
    const float* b1  = (const float*)d_in[ib1];
    const float* W2  = (const float*)d_in[iw2];
    const float* as2 = (const float*)d_in[ias2];
    const float* ad2 = (const float*)d_in[iad2];
    const float* b2  = (const float*)d_in[ib2];
    float*       out = (float*)d_out;

    const int Hd  = in_sizes[ias1];         // 64
    const int Fin = in_sizes[iw1] / Hd;     // 128
    const int N   = in_sizes[ix] / Fin;     // 50000
    const int E   = in_sizes[ie] / 2;       // 800000

    // real device addresses for __device__ globals passed as kernel args
    float* p_x2 = nullptr;
    cudaGetSymbolAddress((void**)&p_x2, g_x2);

    const int B_E    = (E + 255) / 256;
    const int B_NM   = (NMAX + 255) / 256;
    const int B_WARP = (N * 32 + 255) / 256;
    const int B_ROWS = (N + 15) / 16;

    // edge ingest + CSR build (shared by both layers)
    k_zero<<<B_NM, 256>>>();
    k_ingest<<<B_E, 256>>>(ei, E, N);
    k_scan<<<1, 1024>>>();
    k_scatter<<<B_E, 256>>>(E);

    // ---- layer 1 ----
    k_gemm64<128><<<B_ROWS, 256>>>(x, W1, as1, ad1, N);
    k_gat<<<B_WARP, 256>>>(b1, p_x2, 1, N);

    // ---- layer 2 ----
    k_gemm64<64><<<B_ROWS, 256>>>(p_x2, W2, as2, ad2, N);
    k_gat<<<B_WARP, 256>>>(b2, out, 0, N);
}